// round 17
// baseline (speedup 1.0000x reference)
#include <cuda_runtime.h>
#include <math.h>

#define FULL_MASK 0xffffffffu

constexpr int HW = 256;   // 16x16 grid -> scan length
constexpr int B  = 1024;
constexpr int NE = 6;     // support elems per lane: j = 8*e + q, covers [0,47]

// f32 ops with explicit FTZ semantics (state-affecting products / init).
__device__ __forceinline__ float fmul_ftz(float a, float b) {
    float r; asm("mul.rn.ftz.f32 %0,%1,%2;" : "=f"(r) : "f"(a), "f"(b)); return r;
}
__device__ __forceinline__ float fadd_ftz(float a, float b) {
    float r; asm("add.rn.ftz.f32 %0,%1,%2;" : "=f"(r) : "f"(a), "f"(b)); return r;
}
__device__ __forceinline__ float fdiv_ftz(float a, float b) {
    float r; asm("div.rn.ftz.f32 %0,%1,%2;" : "=f"(r) : "f"(a), "f"(b)); return r;
}
__device__ __forceinline__ float rcp_approx(float x) {
    float r; asm("rcp.approx.ftz.f32 %0, %1;" : "=f"(r) : "f"(x)); return r;
}
__device__ __forceinline__ float fma_ftz(float a, float b, float c) {
    float r; asm("fma.rn.ftz.f32 %0,%1,%2,%3;" : "=f"(r) : "f"(a), "f"(b), "f"(c));
    return r;
}

// Correctly-rounded n/d via shared refined reciprocal y1; final op flushes a
// denormal quotient (div.rn.ftz semantics for our proven operand range).
__device__ __forceinline__ float div_corr_ftz(float n, float d, float y1) {
    const float q0  = __fmul_rn(n, y1);
    const float rem = __fmaf_rn(-q0, d, n);
    return fma_ftz(rem, y1, q0);
}

// pzg = RN(t/d) for integer-valued t in [0,d], d in [1,256], r = refined
// reciprocal (1-ulp accurate). Residual FMA-exact; no ties possible.
__device__ __forceinline__ float int_div_exact(float t, float d, float r) {
    const float a   = __fmul_rn(t, r);
    const float rem = __fmaf_rn(-a, d, t);
    return __fmaf_rn(rem, r, a);
}

// p^e for e in [0,31], identical multiply order to the passing R7-R14 kernels.
__device__ __forceinline__ double binexp_pow(double pd, int e5) {
    double pp = 1.0, ps = pd;
#pragma unroll
    for (int k = 0; k < 5; ++k) { if (e5 & 1) pp *= ps; ps *= ps; e5 >>= 1; }
    return pp;
}

// 4 rows per warp; group g = lane/8 owns one row, q = lane%8. Support element
// e of lane holds count index j = 8e + q. Init zero for j >= 42 (reference's
// approx-pow flush); faithful f32-FTZ dynamics afterwards. A group whose
// p_z sum A hits exact 0 is dead (all tail products flushed); dead groups in
// the generic path produce bit-identical outputs to the closed form.
__global__ __launch_bounds__(32)
void obj_kl_kernel(const float* __restrict__ z_pres,
                   const float* __restrict__ z_prob,
                   float* __restrict__ out)
{
    const int lane = threadIdx.x;
    const int g8   = lane & 24;            // 8 * group
    const int q    = lane & 7;
    const int row  = blockIdx.x * 4 + (lane >> 3);

    const float* pr = z_prob + row * HW;
    const float* zs = z_pres + row * HW;
    float*       op = out    + row * HW;

    // p in f32 exactly as the reference: 1/(exp(2f)+1)
    const float  e2p1 = 7.3890560989306495f + 1.0f;
    const float  pf   = __fdiv_rn(1.0f, e2p1);
    const double pd   = (double)pf;
    double p32 = pd;
#pragma unroll
    for (int k = 0; k < 5; ++k) p32 *= p32;    // p^32, same rounding as R14
    const double omp = 1.0 - pd;

    // cd[e] = f32((1-p) p^j), j = 8e+q, zero for j >= 42 (same init as R14).
    float cd[NE];
#pragma unroll
    for (int e = 0; e < NE; ++e) {
        const int j = 8 * e + q;
        double v;
        if (j < 32) v = omp * binexp_pow(pd, j);
        else        v = omp * binexp_pow(pd, j - 32) * p32;
        cd[e] = (j <= 41) ? (float)v : 0.0f;
    }

    // Faithful FTZ init normalization (intralane tree + 3-level group tree).
    {
        float S = fadd_ftz(fadd_ftz(fadd_ftz(cd[0], cd[1]),
                                    fadd_ftz(cd[2], cd[3])),
                           fadd_ftz(cd[4], cd[5]));
#pragma unroll
        for (int m = 4; m > 0; m >>= 1)
            S = fadd_ftz(S, __shfl_xor_sync(FULL_MASK, S, m, 8));
#pragma unroll
        for (int e = 0; e < NE; ++e) cd[e] = fdiv_ftz(cd[e], S);
    }

    int  csf   = 0;        // group's count_so_far (per-lane copy, exact)
    bool alive = true;
    const float EPSF   = 1e-9f;
    const float LOGEPS = __logf(1e-9f);
    const float qf     = (float)q;

#pragma unroll 1
    for (int c = 0; c < 8; ++c) {
        const int sbase = c * 32;
        float myp[4], cl1k[4], cl0k[4];
#pragma unroll
        for (int k = 0; k < 4; ++k) {
            myp[k]  = pr[sbase + k * 8 + q];
            cl1k[k] = __logf(myp[k] + EPSF);
            cl0k[k] = __logf((1.0f - myp[k]) + EPSF);
        }

        if (!alive) {
#pragma unroll
            for (int k = 0; k < 4; ++k)
                op[sbase + k * 8 + q] =
                    myp[k] * (cl1k[k] - LOGEPS) + (1.0f - myp[k]) * cl0k[k];
            continue;
        }

        // sample bits: 4 ballots cover the chunk's 32 steps x 4 rows
        unsigned bal[4];
#pragma unroll
        for (int k = 0; k < 4; ++k) {
            const float z = zs[sbase + k * 8 + q];
            bal[k] = __ballot_sync(FULL_MASK, rintf(z) != 0.0f);
        }
        const unsigned gm = 0xFFu << g8;
        int cb[5]; cb[0] = csf;
#pragma unroll
        for (int k = 0; k < 4; ++k) cb[k + 1] = cb[k] + __popc(bal[k] & gm);

        const float basef = (float)(HW - sbase);
        // refined reciprocals for this lane's 4 step-denominators (off-chain)
        float rr[4];
#pragma unroll
        for (int k = 0; k < 4; ++k) {
            const float d  = basef - (qf + (float)(8 * k));
            const float y0 = rcp_approx(d);
            rr[k] = __fmaf_rn(y0, __fmaf_rn(-d, y0, 1.0f), y0);
        }

        float mykl[4];
#pragma unroll
        for (int k = 0; k < 4; ++k) {
            if (alive) {
                float Alast = 0.0f;
#pragma unroll
                for (int qq = 0; qq < 8; ++qq) {
                    const int s = k * 8 + qq;
                    const bool sbit = (bal[k] >> (g8 + qq)) & 1;
                    const float csff = (float)(cb[k] +
                        __popc(bal[k] & (((1u << qq) - 1u) << g8)));
                    const float denf = basef - (float)s;
                    const float r = __shfl_sync(FULL_MASK, rr[k], qq, 8);
                    const float base0 = qf - csff;

                    float qe[NE], ne[NE];
#pragma unroll
                    for (int e = 0; e < NE; ++e) {
                        const float t =
                            fminf(fmaxf(base0 + (float)(8 * e), 0.0f), denf);
                        const float pzg = int_div_exact(t, denf, r);
                        qe[e] = fmul_ftz(cd[e], pzg);
                        const float alt = fmul_ftz(cd[e], 1.0f - pzg);
                        ne[e] = sbit ? qe[e] : alt;
                    }
                    float A  = ((qe[0] + qe[1]) + (qe[2] + qe[3])) + (qe[4] + qe[5]);
                    float Bv = ((ne[0] + ne[1]) + (ne[2] + ne[3])) + (ne[4] + ne[5]);
#pragma unroll
                    for (int m = 4; m > 0; m >>= 1) {
                        A  += __shfl_xor_sync(FULL_MASK, A,  m, 8);
                        Bv += __shfl_xor_sync(FULL_MASK, Bv, m, 8);
                    }

                    const float norm = fmaxf(Bv, 1e-6f);
                    const float y0 = rcp_approx(norm);
                    const float ee = __fmaf_rn(-norm, y0, 1.0f);
                    const float y1 = __fmaf_rn(y0, ee, y0);
#pragma unroll
                    for (int e = 0; e < NE; ++e)
                        cd[e] = div_corr_ftz(ne[e], norm, y1);

                    const float m1 = __logf(A + EPSF);
                    const float m0 = __logf((1.0f - A) + EPSF);
                    const float kl = myp[k] * (cl1k[k] - m1)
                                   + (1.0f - myp[k]) * (cl0k[k] - m0);
                    if (q == qq) mykl[k] = kl;
                    Alast = A;
                }
                // Death: A == 0 <=> all surviving support has pzg == 0, which
                // is permanent (revival needs a ~2^-50-probability event).
                if (__all_sync(FULL_MASK, Alast == 0.0f)) alive = false;
            } else {
                mykl[k] = myp[k] * (cl1k[k] - LOGEPS)
                        + (1.0f - myp[k]) * cl0k[k];
            }
        }
        csf = cb[4];
#pragma unroll
        for (int k = 0; k < 4; ++k) op[sbase + k * 8 + q] = mykl[k];
    }
}

extern "C" void kernel_launch(void* const* d_in, const int* in_sizes, int n_in,
                              void* d_out, int out_size) {
    const float* z_pres = (const float*)d_in[0];   // z_pres      [B,1,16,16]
    const float* z_prob = (const float*)d_in[1];   // z_pres_prob [B,1,16,16]
    float*       out    = (float*)d_out;           // obj_kl      [B,1,16,16]
    obj_kl_kernel<<<B / 4, 32>>>(z_pres, z_prob, out);
}